// round 7
// baseline (speedup 1.0000x reference)
#include <cuda_runtime.h>
#include <math.h>
#include <stdint.h>

#define Bc 16
#define Lc 2048
#define Dc 192
#define Hc 4
#define Kc 12

// ---------------- scratch (no allocations allowed) ----------------
__device__ float g_xn [(size_t)Bc*Lc*Dc];       // xn2 (written by fused proj+LN2)
__device__ float g_q  [(size_t)Bc*Hc*Lc*Kc];    // [B,H,L,K]
__device__ float g_k  [(size_t)Bc*Hc*Lc*Kc];
__device__ float g_v  [(size_t)Bc*Hc*Lc*Kc];
__device__ float g_ctx[(size_t)Bc*Lc*Hc*Kc];    // [B,L,H,K]
__device__ float g_y1 [(size_t)Bc*Lc*Dc];       // x + MHA
__device__ float g_h  [(size_t)Bc*Lc*Dc];       // relu(conv1), zero rows 0, L-1

__device__ __forceinline__ float ex2(float x) {
    float y; asm("ex2.approx.f32 %0, %1;" : "=f"(y) : "f"(x)); return y;
}
__device__ __forceinline__ float to_tf32(float x) {
    uint32_t u; asm("cvt.rna.tf32.f32 %0, %1;" : "=r"(u) : "f"(x));
    return __uint_as_float(u);
}
__device__ __forceinline__ void mma_tf32(float* c, const uint32_t* a,
                                         uint32_t b0, uint32_t b1)
{
    asm volatile(
        "mma.sync.aligned.m16n8k8.row.col.f32.tf32.tf32.f32 "
        "{%0,%1,%2,%3}, {%4,%5,%6,%7}, {%8,%9}, {%0,%1,%2,%3};"
        : "+f"(c[0]), "+f"(c[1]), "+f"(c[2]), "+f"(c[3])
        : "r"(a[0]), "r"(a[1]), "r"(a[2]), "r"(a[3]), "r"(b0), "r"(b1));
}
// ---- packed f32x2 (Blackwell FFMA2 pipe; rn rounding == scalar FFMA) ----
__device__ __forceinline__ uint64_t pack2(float x, float y) {
    uint64_t r; asm("mov.b64 %0, {%1, %2};" : "=l"(r) : "f"(x), "f"(y)); return r;
}
__device__ __forceinline__ float2 unpack2(uint64_t v) {
    float x, y; asm("mov.b64 {%0, %1}, %2;" : "=f"(x), "=f"(y) : "l"(v));
    return make_float2(x, y);
}
__device__ __forceinline__ uint64_t fma2(uint64_t a, uint64_t b, uint64_t c) {
    uint64_t d;
    asm("fma.rn.f32x2 %0, %1, %2, %3;" : "=l"(d) : "l"(a), "l"(b), "l"(c));
    return d;
}

// ---------------- QKV projection + fused LN1: tf32 MMA ----------------
// M=64/block, N=3x48, K=192. 192 threads = 6 warps.
#define QA_S 196
#define QB_S 152
#define QA_FLOATS (64 * QA_S)
#define QB_FLOATS (32 * QB_S)
#define QKV_SMEM_BYTES ((QA_FLOATS + 2 * QB_FLOATS) * 4)

__global__ __launch_bounds__(192, 2)
void qkv_mma_kernel(const float* __restrict__ x,
                    const float* __restrict__ ln_g, const float* __restrict__ ln_b,
                    const float* __restrict__ wq, const float* __restrict__ bq,
                    const float* __restrict__ wk, const float* __restrict__ bk,
                    const float* __restrict__ wv, const float* __restrict__ bv)
{
    extern __shared__ float smem[];
    float* sA = smem;                 // [64][196] raw x rows -> LN'd tf32 in-place
    float* sB = smem + QA_FLOATS;     // [2][32][152] tf32 weights (q|k|v cols)

    const int tid  = threadIdx.x;
    const int w    = tid >> 5;
    const int lane = tid & 31;
    const int tig  = lane & 3;
    const int grp  = lane >> 2;
    const int rowbase = blockIdx.x * 64;
    const int bb   = rowbase / Lc;
    const int lloc = rowbase % Lc;

    auto loadW = [&](int kc, int bf) {
        float* dstb = sB + bf * QB_FLOATS;
#pragma unroll
        for (int it = 0; it < 6; it++) {
            int idx = tid + it * 192;            // 32*36 float4 = 1152
            int k = idx / 36, c = (idx % 36) * 4;
            int m = c / 48, lc = c % 48;
            const float* src = (m == 0) ? wq : (m == 1) ? wk : wv;
            float4 v = *(const float4*)(src + (size_t)(kc * 32 + k) * 48 + lc);
            float* d = dstb + k * QB_S + c;
            d[0] = to_tf32(v.x); d[1] = to_tf32(v.y);
            d[2] = to_tf32(v.z); d[3] = to_tf32(v.w);
        }
    };

    // raw x rows into sA (fp32), plus first weight chunk
    for (int idx = tid; idx < 64 * 48; idx += 192) {
        int r = idx / 48, c4 = (idx % 48) * 4;
        *(float4*)(sA + r * QA_S + c4) =
            *(const float4*)(x + (size_t)(rowbase + r) * Dc + c4);
    }
    loadW(0, 0);
    __syncthreads();

    // fused LN1: warp w handles rows w, w+6, ...
    for (int r = w; r < 64; r += 6) {
        float vv[6]; float s = 0.f;
#pragma unroll
        for (int i = 0; i < 6; i++) { vv[i] = sA[r * QA_S + lane + 32*i]; s += vv[i]; }
#pragma unroll
        for (int o = 16; o; o >>= 1) s += __shfl_xor_sync(0xffffffffu, s, o);
        float mean = s * (1.f/192.f);
        float vs = 0.f;
#pragma unroll
        for (int i = 0; i < 6; i++) { float dd = vv[i] - mean; vs += dd*dd; }
#pragma unroll
        for (int o = 16; o; o >>= 1) vs += __shfl_xor_sync(0xffffffffu, vs, o);
        float inv = rsqrtf(vs * (1.f/192.f) + 1e-3f);
#pragma unroll
        for (int i = 0; i < 6; i++) {
            int c = lane + 32*i;
            sA[r * QA_S + c] = to_tf32((vv[i] - mean) * inv * ln_g[c] + ln_b[c]);
        }
    }
    __syncthreads();

    const int s     = w >> 1;
    const int mbase = (w & 1) * 32;
    float c[2][6][4];
#pragma unroll
    for (int i = 0; i < 2; i++)
#pragma unroll
        for (int j = 0; j < 6; j++)
#pragma unroll
            for (int q = 0; q < 4; q++) c[i][j][q] = 0.f;

    int buf = 0;
    for (int kc = 0; kc < 6; kc++) {
        if (kc < 5) loadW(kc + 1, buf ^ 1);
        const float* bBuf = sB + buf * QB_FLOATS + s * 48;
#pragma unroll
        for (int ks = 0; ks < 4; ks++) {
            const int c0 = kc * 32 + ks * 8;
            uint32_t a[2][4];
#pragma unroll
            for (int mt = 0; mt < 2; mt++) {
                const float* ap = sA + (mbase + mt * 16 + grp) * QA_S + c0 + tig;
                a[mt][0] = __float_as_uint(ap[0]);
                a[mt][1] = __float_as_uint(ap[8 * QA_S]);
                a[mt][2] = __float_as_uint(ap[4]);
                a[mt][3] = __float_as_uint(ap[8 * QA_S + 4]);
            }
            const float* bp = bBuf + (ks * 8 + tig) * QB_S + grp;
#pragma unroll
            for (int nt = 0; nt < 6; nt++) {
                uint32_t b0 = __float_as_uint(bp[nt * 8]);
                uint32_t b1 = __float_as_uint(bp[nt * 8 + 4 * QB_S]);
                mma_tf32(c[0][nt], a[0], b0, b1);
                mma_tf32(c[1][nt], a[1], b0, b1);
            }
        }
        __syncthreads();
        buf ^= 1;
    }

    const float* Bp = (s == 0) ? bq : (s == 1) ? bk : bv;
    float* O = (s == 0) ? g_q : (s == 1) ? g_k : g_v;
#pragma unroll
    for (int mt = 0; mt < 2; mt++) {
#pragma unroll
        for (int rs = 0; rs < 2; rs++) {
            int l = lloc + mbase + mt * 16 + grp + rs * 8;
#pragma unroll
            for (int nt = 0; nt < 6; nt++) {
                int n = nt * 8 + tig * 2;       // 0..47, even
                int h = n / 12, kk = n % 12;
                float2 res;
                res.x = c[mt][nt][rs * 2 + 0] + Bp[n];
                res.y = c[mt][nt][rs * 2 + 1] + Bp[n + 1];
                *(float2*)(O + (((size_t)bb * Hc + h) * Lc + l) * Kc + kk) = res;
            }
        }
    }
}

// ---------------- causal attention: 4 queries/thread, FFMA2 ----------------
// queries l_i = 512*qt + t + 128*i.  J: i<J skip, i==J masked (mm<=t), i>J full.
// J=-1 -> all full.
template<int J>
__device__ __forceinline__ void attn_tile4(const float4* __restrict__ sk,
                                           const float4* __restrict__ sv,
                                           int t, const uint64_t q2[4][6],
                                           uint64_t o2[4][6], float* d)
{
#pragma unroll 2
    for (int mm = 0; mm < 128; mm++) {
        float4 ka = sk[3*mm], kb = sk[3*mm+1], kc = sk[3*mm+2];
        uint64_t k2[6] = { pack2(ka.x, ka.y), pack2(ka.z, ka.w),
                           pack2(kb.x, kb.y), pack2(kb.z, kb.w),
                           pack2(kc.x, kc.y), pack2(kc.z, kc.w) };
        float4 va = sv[3*mm], vb = sv[3*mm+1], vc = sv[3*mm+2];
        uint64_t v2[6] = { pack2(va.x, va.y), pack2(va.z, va.w),
                           pack2(vb.x, vb.y), pack2(vb.z, vb.w),
                           pack2(vc.x, vc.y), pack2(vc.z, vc.w) };
        float p[4];
#pragma unroll
        for (int i = 0; i < 4; i++) {
            if (i < J) continue;
            uint64_t accA = fma2(q2[i][0], k2[0], 0ull);
            uint64_t accB = fma2(q2[i][1], k2[1], 0ull);
            accA = fma2(q2[i][2], k2[2], accA);
            accB = fma2(q2[i][3], k2[3], accB);
            accA = fma2(q2[i][4], k2[4], accA);
            accB = fma2(q2[i][5], k2[5], accB);
            float2 aa = unpack2(accA), bb = unpack2(accB);
            float s = (aa.x + aa.y) + (bb.x + bb.y);
            p[i] = ex2(s);
            if (i == J && mm > t) p[i] = 0.f;
            d[i] += p[i];
        }
#pragma unroll
        for (int i = 0; i < 4; i++) {
            if (i < J) continue;
            uint64_t p2 = pack2(p[i], p[i]);
#pragma unroll
            for (int j = 0; j < 6; j++) o2[i][j] = fma2(p2, v2[j], o2[i][j]);
        }
    }
}

__global__ void attn_kernel()
{
    __shared__ float4 sk[128 * 3];
    __shared__ float4 sv[128 * 3];
    int qt = gridDim.x - 1 - blockIdx.x;    // heavy tiles first
    int h = blockIdx.y, bb = blockIdx.z;
    int t = threadIdx.x;

    size_t head = ((size_t)bb * Hc + h) * Lc * Kc;
    const float4* qb = (const float4*)(g_q + head);
    const float*  kb = g_k + head;
    const float*  vb = g_v + head;

    const float scale = 0.4164682333693345f;   // log2(e)/sqrt(12)
    uint64_t q2[4][6], o2[4][6];
    float d[4];
#pragma unroll
    for (int i = 0; i < 4; i++) {
        int l = qt * 512 + t + 128 * i;
        float4 a = qb[3*l], b = qb[3*l+1], c = qb[3*l+2];
        q2[i][0] = pack2(a.x*scale, a.y*scale);
        q2[i][1] = pack2(a.z*scale, a.w*scale);
        q2[i][2] = pack2(b.x*scale, b.y*scale);
        q2[i][3] = pack2(b.z*scale, b.w*scale);
        q2[i][4] = pack2(c.x*scale, c.y*scale);
        q2[i][5] = pack2(c.z*scale, c.w*scale);
        d[i] = 0.f;
#pragma unroll
        for (int j = 0; j < 6; j++) o2[i][j] = 0ull;
    }

    int full = 4 * qt;
    for (int kt = 0; kt < full + 4; kt++) {
        __syncthreads();
        const float4* ks = (const float4*)(kb + (size_t)kt * 128 * Kc);
        const float4* vs = (const float4*)(vb + (size_t)kt * 128 * Kc);
        for (int i = t; i < 128 * 3; i += 128) { sk[i] = ks[i]; sv[i] = vs[i]; }
        __syncthreads();
        if      (kt <  full)     attn_tile4<-1>(sk, sv, t, q2, o2, d);
        else if (kt == full)     attn_tile4<0>(sk, sv, t, q2, o2, d);
        else if (kt == full + 1) attn_tile4<1>(sk, sv, t, q2, o2, d);
        else if (kt == full + 2) attn_tile4<2>(sk, sv, t, q2, o2, d);
        else                     attn_tile4<3>(sk, sv, t, q2, o2, d);
    }

#pragma unroll
    for (int i = 0; i < 4; i++) {
        float inv = 1.f / d[i];
        int l = qt * 512 + t + 128 * i;
        float4* out = (float4*)(g_ctx + (((size_t)bb * Lc + l) * Hc + h) * Kc);
        float2 p0 = unpack2(o2[i][0]), p1 = unpack2(o2[i][1]);
        float2 p2_ = unpack2(o2[i][2]), p3 = unpack2(o2[i][3]);
        float2 p4 = unpack2(o2[i][4]), p5 = unpack2(o2[i][5]);
        out[0] = make_float4(p0.x*inv, p0.y*inv, p1.x*inv, p1.y*inv);
        out[1] = make_float4(p2_.x*inv, p2_.y*inv, p3.x*inv, p3.y*inv);
        out[2] = make_float4(p4.x*inv, p4.y*inv, p5.x*inv, p5.y*inv);
    }
}

// ---------------- output projection + residual + fused LN2: tf32 MMA ----------
// M=64/block, N=192, K=48. 256 threads = 8 warps. After MMA: stage y1 in smem,
// row-wise LN -> g_xn (xn2, fp32); g_y1 written from registers.
#define PA_S 52
#define PB_S 200
#define PA_FLOATS (64 * PA_S)
#define PB_FLOATS (48 * PB_S)
#define PST_S 196
#define PROJ_SMEM_BYTES ((PA_FLOATS + PB_FLOATS) * 4)   // 12928 floats > 64*196

__global__ __launch_bounds__(256, 4)
void proj_mma_kernel(const float* __restrict__ x,
                     const float* __restrict__ wo,
                     const float* __restrict__ bo,
                     const float* __restrict__ ln_g,
                     const float* __restrict__ ln_b)
{
    extern __shared__ float smem[];
    float* sA = smem;                 // [64][52]  ctx rows, tf32
    float* sB = smem + PA_FLOATS;     // [48][200] wo, tf32

    const int tid  = threadIdx.x;
    const int w    = tid >> 5;
    const int lane = tid & 31;
    const int tig  = lane & 3;
    const int grp  = lane >> 2;
    const int rowbase = blockIdx.x * 64;

    for (int idx = tid; idx < 64 * 12; idx += 256) {
        int r = idx / 12, c4 = (idx % 12) * 4;
        float4 v = *(const float4*)(g_ctx + (size_t)(rowbase + r) * 48 + c4);
        float* d = sA + r * PA_S + c4;
        d[0] = to_tf32(v.x); d[1] = to_tf32(v.y);
        d[2] = to_tf32(v.z); d[3] = to_tf32(v.w);
    }
    for (int idx = tid; idx < 48 * 48; idx += 256) {
        int r = idx / 48, c4 = (idx % 48) * 4;
        float4 v = *(const float4*)(wo + (size_t)r * Dc + c4);
        float* d = sB + r * PB_S + c4;
        d[0] = to_tf32(v.x); d[1] = to_tf32(v.y);
        d[2] = to_tf32(v.z); d[3] = to_tf32(v.w);
    }
    __syncthreads();

    const int mbase = (w & 1) * 32;
    const int nbase = (w >> 1) * 48;
    float c[2][6][4];
#pragma unroll
    for (int i = 0; i < 2; i++)
#pragma unroll
        for (int j = 0; j < 6; j++)
#pragma unroll
            for (int q = 0; q < 4; q++) c[i][j][q] = 0.f;

#pragma unroll
    for (int ks = 0; ks < 6; ks++) {
        const int c0 = ks * 8;
        uint32_t a[2][4];
#pragma unroll
        for (int mt = 0; mt < 2; mt++) {
            const float* ap = sA + (mbase + mt * 16 + grp) * PA_S + c0 + tig;
            a[mt][0] = __float_as_uint(ap[0]);
            a[mt][1] = __float_as_uint(ap[8 * PA_S]);
            a[mt][2] = __float_as_uint(ap[4]);
            a[mt][3] = __float_as_uint(ap[8 * PA_S + 4]);
        }
        const float* bp = sB + (c0 + tig) * PB_S + nbase + grp;
#pragma unroll
        for (int nt = 0; nt < 6; nt++) {
            uint32_t b0 = __float_as_uint(bp[nt * 8]);
            uint32_t b1 = __float_as_uint(bp[nt * 8 + 4 * PB_S]);
            mma_tf32(c[0][nt], a[0], b0, b1);
            mma_tf32(c[1][nt], a[1], b0, b1);
        }
    }
    __syncthreads();                       // done with sA/sB; reuse as stage

    float* stage = smem;                   // [64][196]
#pragma unroll
    for (int mt = 0; mt < 2; mt++) {
#pragma unroll
        for (int rs = 0; rs < 2; rs++) {
            int r = mbase + mt * 16 + grp + rs * 8;
            size_t off = (size_t)(rowbase + r) * Dc;
#pragma unroll
            for (int nt = 0; nt < 6; nt++) {
                int n = nbase + nt * 8 + tig * 2;
                float2 xv = *(const float2*)(x + off + n);
                float2 res;
                res.x = c[mt][nt][rs * 2 + 0] + bo[n]     + xv.x;
                res.y = c[mt][nt][rs * 2 + 1] + bo[n + 1] + xv.y;
                *(float2*)(g_y1 + off + n) = res;
                *(float2*)(stage + r * PST_S + n) = res;
            }
        }
    }
    __syncthreads();

    // fused LN2: warp w handles rows w, w+8, ... -> g_xn (fp32)
    for (int r = w; r < 64; r += 8) {
        float vv[6]; float s = 0.f;
#pragma unroll
        for (int i = 0; i < 6; i++) { vv[i] = stage[r * PST_S + lane + 32*i]; s += vv[i]; }
#pragma unroll
        for (int o = 16; o; o >>= 1) s += __shfl_xor_sync(0xffffffffu, s, o);
        float mean = s * (1.f/192.f);
        float vs = 0.f;
#pragma unroll
        for (int i = 0; i < 6; i++) { float dd = vv[i] - mean; vs += dd*dd; }
#pragma unroll
        for (int o = 16; o; o >>= 1) vs += __shfl_xor_sync(0xffffffffu, vs, o);
        float inv = rsqrtf(vs * (1.f/192.f) + 1e-3f);
#pragma unroll
        for (int i = 0; i < 6; i++) {
            int cc = lane + 32*i;
            g_xn[(size_t)(rowbase + r) * Dc + cc] =
                (vv[i] - mean) * inv * ln_g[cc] + ln_b[cc];
        }
    }
}

// ---------------- conv1d as tf32 tensor-core GEMM ----------------
#define SA_STRIDE 196
#define SB_STRIDE 200
#define SA_FLOATS (66 * SA_STRIDE)
#define SB_FLOATS (32 * SB_STRIDE)
#define CONV_SMEM_BYTES ((SA_FLOATS + 2 * SB_FLOATS) * 4)

template<int MODE>
__global__ __launch_bounds__(256, 2)
void conv_mma_kernel(const float* __restrict__ W,
                     const float* __restrict__ bias,
                     float* __restrict__ out)
{
    extern __shared__ float smem[];
    float* sA = smem;                    // [66][196]
    float* sB = smem + SA_FLOATS;        // [2][32][200]

    const int tid  = threadIdx.x;
    const int w    = tid >> 5;
    const int lane = tid & 31;
    const int tig  = lane & 3;
    const int grp  = lane >> 2;
    const int l0   = blockIdx.x * 64;
    const int bb   = blockIdx.y;
    const float* srcb = ((MODE == 0) ? g_xn : g_h) + (size_t)bb * Lc * Dc;

    for (int idx = tid; idx < 66 * 48; idx += 256) {
        int r = idx / 48, c4 = (idx % 48) * 4;
        int l = l0 - 1 + r; l = l < 0 ? 0 : (l > Lc - 1 ? Lc - 1 : l);
        float4 v = *(const float4*)(srcb + (size_t)l * Dc + c4);
        float* d = sA + r * SA_STRIDE + c4;
        d[0] = to_tf32(v.x); d[1] = to_tf32(v.y);
        d[2] = to_tf32(v.z); d[3] = to_tf32(v.w);
    }

    const int mbase = (w & 1) * 32;
    const int nbase = (w >> 1) * 48;
    float c[2][6][4];
#pragma unroll
    for (int i = 0; i < 2; i++)
#pragma unroll
        for (int j = 0; j < 6; j++)
#pragma unroll
            for (int q = 0; q < 4; q++) c[i][j][q] = 0.f;

    auto loadW = [&](int kc, int bf) {
        float* dstb = sB + bf * SB_FLOATS;
#pragma unroll
        for (int it = 0; it < 6; it++) {
            int idx = tid + it * 256;
            int k = idx / 48, c4 = (idx % 48) * 4;
            float4 v = *(const float4*)(W + ((size_t)(kc * 32 + k)) * Dc + c4);
            float* d = dstb + k * SB_STRIDE + c4;
            d[0] = to_tf32(v.x); d[1] = to_tf32(v.y);
            d[2] = to_tf32(v.z); d[3] = to_tf32(v.w);
        }
    };

    loadW(0, 0);
    __syncthreads();

    int buf = 0;
    for (int kc = 0; kc < 18; kc++) {
        if (kc < 17) loadW(kc + 1, buf ^ 1);
        const int t  = kc / 6;
        const int cc = (kc % 6) * 32;
        const float* bBuf = sB + buf * SB_FLOATS;
#pragma unroll
        for (int ks = 0; ks < 4; ks++) {
            const int c0 = cc + ks * 8;
            uint32_t a[2][4];
#pragma unroll
            for (int mt = 0; mt < 2; mt++) {
                const float* ap = sA + (mbase + mt * 16 + grp + t) * SA_STRIDE + c0 + tig;
                a[mt][0] = __float_as_uint(ap[0]);
                a[mt][1] = __float_as_uint(ap[8 * SA_STRIDE]);
                a[mt][2] = __float_as_uint(ap[4]);
                a[mt][3] = __float_as_uint(ap[8 * SA_STRIDE + 4]);
            }
            const float* bp = bBuf + (ks * 8 + tig) * SB_STRIDE + nbase + grp;
#pragma unroll
            for (int nt = 0; nt < 6; nt++) {
                uint32_t b0 = __float_as_uint(bp[nt * 8]);
                uint32_t b1 = __float_as_uint(bp[nt * 8 + 4 * SB_STRIDE]);
                mma_tf32(c[0][nt], a[0], b0, b1);
                mma_tf32(c[1][nt], a[1], b0, b1);
            }
        }
        __syncthreads();
        buf ^= 1;
    }

    float* dst = (MODE == 0) ? g_h : out;
#pragma unroll
    for (int mt = 0; mt < 2; mt++) {
#pragma unroll
        for (int rs = 0; rs < 2; rs++) {
            int l = l0 + mbase + mt * 16 + grp + rs * 8;
            bool interior = (l >= 1) && (l <= Lc - 2);
            size_t rowoff = ((size_t)bb * Lc + l) * Dc;
#pragma unroll
            for (int nt = 0; nt < 6; nt++) {
                int n = nbase + nt * 8 + tig * 2;
                float v0 = c[mt][nt][rs * 2 + 0] + bias[n];
                float v1 = c[mt][nt][rs * 2 + 1] + bias[n + 1];
                float2 res;
                if (MODE == 0) {
                    res.x = interior ? fmaxf(v0, 0.f) : 0.f;
                    res.y = interior ? fmaxf(v1, 0.f) : 0.f;
                } else {
                    float2 y = *(const float2*)(g_y1 + rowoff + n);
                    res.x = y.x + (interior ? v0 : 0.f);
                    res.y = y.y + (interior ? v1 : 0.f);
                }
                *(float2*)(dst + rowoff + n) = res;
            }
        }
    }
}

// ---------------- launcher ----------------
extern "C" void kernel_launch(void* const* d_in, const int* in_sizes, int n_in,
                              void* d_out, int out_size)
{
    const float* x     = (const float*)d_in[0];
    const float* ln1_g = (const float*)d_in[1];
    const float* ln1_b = (const float*)d_in[2];
    const float* wq    = (const float*)d_in[3];
    const float* bq    = (const float*)d_in[4];
    const float* wk    = (const float*)d_in[5];
    const float* bk    = (const float*)d_in[6];
    const float* wv    = (const float*)d_in[7];
    const float* bv    = (const float*)d_in[8];
    const float* wo    = (const float*)d_in[9];
    const float* bo    = (const float*)d_in[10];
    const float* ln2_g = (const float*)d_in[11];
    const float* ln2_b = (const float*)d_in[12];
    const float* c1_w  = (const float*)d_in[13];
    const float* c1_b  = (const float*)d_in[14];
    const float* c2_w  = (const float*)d_in[15];
    const float* c2_b  = (const float*)d_in[16];
    float* outp = (float*)d_out;

    cudaFuncSetAttribute(conv_mma_kernel<0>,
                         cudaFuncAttributeMaxDynamicSharedMemorySize, CONV_SMEM_BYTES);
    cudaFuncSetAttribute(conv_mma_kernel<1>,
                         cudaFuncAttributeMaxDynamicSharedMemorySize, CONV_SMEM_BYTES);
    cudaFuncSetAttribute(qkv_mma_kernel,
                         cudaFuncAttributeMaxDynamicSharedMemorySize, QKV_SMEM_BYTES);
    cudaFuncSetAttribute(proj_mma_kernel,
                         cudaFuncAttributeMaxDynamicSharedMemorySize, PROJ_SMEM_BYTES);

    qkv_mma_kernel<<<(Bc*Lc)/64, 192, QKV_SMEM_BYTES>>>(x, ln1_g, ln1_b,
                                                        wq, bq, wk, bk, wv, bv);
    attn_kernel<<<dim3(Lc/512, Hc, Bc), 128>>>();
    proj_mma_kernel<<<(Bc*Lc)/64, 256, PROJ_SMEM_BYTES>>>(x, wo, bo, ln2_g, ln2_b);
    conv_mma_kernel<0><<<dim3(Lc/64, Bc), 256, CONV_SMEM_BYTES>>>(c1_w, c1_b, outp);
    conv_mma_kernel<1><<<dim3(Lc/64, Bc), 256, CONV_SMEM_BYTES>>>(c2_w, c2_b, outp);
}

// round 8
// speedup vs baseline: 1.0938x; 1.0938x over previous
#include <cuda_runtime.h>
#include <math.h>
#include <stdint.h>

#define Bc 16
#define Lc 2048
#define Dc 192
#define Hc 4
#define Kc 12

// ---------------- scratch (no allocations allowed) ----------------
__device__ float g_xn [(size_t)Bc*Lc*Dc];       // xn2 (written by fused proj+LN2)
__device__ float g_q  [(size_t)Bc*Hc*Lc*Kc];    // [B,H,L,K]
__device__ float g_k  [(size_t)Bc*Hc*Lc*Kc];
__device__ float g_v  [(size_t)Bc*Hc*Lc*Kc];
__device__ float g_ctx[(size_t)Bc*Lc*Hc*Kc];    // [B,L,H,K]
__device__ float g_y1 [(size_t)Bc*Lc*Dc];       // x + MHA
__device__ float g_h  [(size_t)Bc*Lc*Dc];       // relu(conv1), zero rows 0, L-1

__device__ __forceinline__ float ex2(float x) {
    float y; asm("ex2.approx.f32 %0, %1;" : "=f"(y) : "f"(x)); return y;
}
__device__ __forceinline__ float to_tf32(float x) {
    uint32_t u; asm("cvt.rna.tf32.f32 %0, %1;" : "=r"(u) : "f"(x));
    return __uint_as_float(u);
}
__device__ __forceinline__ void mma_tf32(float* c, const uint32_t* a,
                                         uint32_t b0, uint32_t b1)
{
    asm volatile(
        "mma.sync.aligned.m16n8k8.row.col.f32.tf32.tf32.f32 "
        "{%0,%1,%2,%3}, {%4,%5,%6,%7}, {%8,%9}, {%0,%1,%2,%3};"
        : "+f"(c[0]), "+f"(c[1]), "+f"(c[2]), "+f"(c[3])
        : "r"(a[0]), "r"(a[1]), "r"(a[2]), "r"(a[3]), "r"(b0), "r"(b1));
}

// ---------------- QKV projection + fused LN1: tf32 MMA ----------------
// M=64/block, N=3x48, K=192. 192 threads = 6 warps.
#define QA_S 196
#define QB_S 152
#define QA_FLOATS (64 * QA_S)
#define QB_FLOATS (32 * QB_S)
#define QKV_SMEM_BYTES ((QA_FLOATS + 2 * QB_FLOATS) * 4)

__global__ __launch_bounds__(192, 2)
void qkv_mma_kernel(const float* __restrict__ x,
                    const float* __restrict__ ln_g, const float* __restrict__ ln_b,
                    const float* __restrict__ wq, const float* __restrict__ bq,
                    const float* __restrict__ wk, const float* __restrict__ bk,
                    const float* __restrict__ wv, const float* __restrict__ bv)
{
    extern __shared__ float smem[];
    float* sA = smem;                 // [64][196] raw x rows -> LN'd tf32 in-place
    float* sB = smem + QA_FLOATS;     // [2][32][152] tf32 weights (q|k|v cols)

    const int tid  = threadIdx.x;
    const int w    = tid >> 5;
    const int lane = tid & 31;
    const int tig  = lane & 3;
    const int grp  = lane >> 2;
    const int rowbase = blockIdx.x * 64;
    const int bb   = rowbase / Lc;
    const int lloc = rowbase % Lc;

    auto loadW = [&](int kc, int bf) {
        float* dstb = sB + bf * QB_FLOATS;
#pragma unroll
        for (int it = 0; it < 6; it++) {
            int idx = tid + it * 192;            // 32*36 float4 = 1152
            int k = idx / 36, c = (idx % 36) * 4;
            int m = c / 48, lc = c % 48;
            const float* src = (m == 0) ? wq : (m == 1) ? wk : wv;
            float4 v = *(const float4*)(src + (size_t)(kc * 32 + k) * 48 + lc);
            float* d = dstb + k * QB_S + c;
            d[0] = to_tf32(v.x); d[1] = to_tf32(v.y);
            d[2] = to_tf32(v.z); d[3] = to_tf32(v.w);
        }
    };

    // raw x rows into sA (fp32), plus first weight chunk
    for (int idx = tid; idx < 64 * 48; idx += 192) {
        int r = idx / 48, c4 = (idx % 48) * 4;
        *(float4*)(sA + r * QA_S + c4) =
            *(const float4*)(x + (size_t)(rowbase + r) * Dc + c4);
    }
    loadW(0, 0);
    __syncthreads();

    // fused LN1: warp w handles rows w, w+6, ...
    for (int r = w; r < 64; r += 6) {
        float vv[6]; float s = 0.f;
#pragma unroll
        for (int i = 0; i < 6; i++) { vv[i] = sA[r * QA_S + lane + 32*i]; s += vv[i]; }
#pragma unroll
        for (int o = 16; o; o >>= 1) s += __shfl_xor_sync(0xffffffffu, s, o);
        float mean = s * (1.f/192.f);
        float vs = 0.f;
#pragma unroll
        for (int i = 0; i < 6; i++) { float dd = vv[i] - mean; vs += dd*dd; }
#pragma unroll
        for (int o = 16; o; o >>= 1) vs += __shfl_xor_sync(0xffffffffu, vs, o);
        float inv = rsqrtf(vs * (1.f/192.f) + 1e-3f);
#pragma unroll
        for (int i = 0; i < 6; i++) {
            int c = lane + 32*i;
            sA[r * QA_S + c] = to_tf32((vv[i] - mean) * inv * ln_g[c] + ln_b[c]);
        }
    }
    __syncthreads();

    const int s     = w >> 1;
    const int mbase = (w & 1) * 32;
    float c[2][6][4];
#pragma unroll
    for (int i = 0; i < 2; i++)
#pragma unroll
        for (int j = 0; j < 6; j++)
#pragma unroll
            for (int q = 0; q < 4; q++) c[i][j][q] = 0.f;

    int buf = 0;
    for (int kc = 0; kc < 6; kc++) {
        if (kc < 5) loadW(kc + 1, buf ^ 1);
        const float* bBuf = sB + buf * QB_FLOATS + s * 48;
#pragma unroll
        for (int ks = 0; ks < 4; ks++) {
            const int c0 = kc * 32 + ks * 8;
            uint32_t a[2][4];
#pragma unroll
            for (int mt = 0; mt < 2; mt++) {
                const float* ap = sA + (mbase + mt * 16 + grp) * QA_S + c0 + tig;
                a[mt][0] = __float_as_uint(ap[0]);
                a[mt][1] = __float_as_uint(ap[8 * QA_S]);
                a[mt][2] = __float_as_uint(ap[4]);
                a[mt][3] = __float_as_uint(ap[8 * QA_S + 4]);
            }
            const float* bp = bBuf + (ks * 8 + tig) * QB_S + grp;
#pragma unroll
            for (int nt = 0; nt < 6; nt++) {
                uint32_t b0 = __float_as_uint(bp[nt * 8]);
                uint32_t b1 = __float_as_uint(bp[nt * 8 + 4 * QB_S]);
                mma_tf32(c[0][nt], a[0], b0, b1);
                mma_tf32(c[1][nt], a[1], b0, b1);
            }
        }
        __syncthreads();
        buf ^= 1;
    }

    const float* Bp = (s == 0) ? bq : (s == 1) ? bk : bv;
    float* O = (s == 0) ? g_q : (s == 1) ? g_k : g_v;
#pragma unroll
    for (int mt = 0; mt < 2; mt++) {
#pragma unroll
        for (int rs = 0; rs < 2; rs++) {
            int l = lloc + mbase + mt * 16 + grp + rs * 8;
#pragma unroll
            for (int nt = 0; nt < 6; nt++) {
                int n = nt * 8 + tig * 2;       // 0..47, even
                int h = n / 12, kk = n % 12;
                float2 res;
                res.x = c[mt][nt][rs * 2 + 0] + Bp[n];
                res.y = c[mt][nt][rs * 2 + 1] + Bp[n + 1];
                *(float2*)(O + (((size_t)bb * Hc + h) * Lc + l) * Kc + kk) = res;
            }
        }
    }
}

// ---------------- causal attention: 4 queries/thread (scalar, R6-proven) -------
// queries l_i = 512*qt + t + 128*i.  J: i<J skip, i==J masked (mm<=t), i>J full.
// J=-1 -> all full.
template<int J>
__device__ __forceinline__ void attn_tile4(const float4* __restrict__ sk,
                                           const float4* __restrict__ sv,
                                           int t, const float q[4][12],
                                           float o[4][12], float* d)
{
#pragma unroll 2
    for (int mm = 0; mm < 128; mm++) {
        float4 ka = sk[3*mm], kb = sk[3*mm+1], kc = sk[3*mm+2];
        float p[4];
#pragma unroll
        for (int i = 0; i < 4; i++) {
            if (i < J) continue;
            float s = q[i][0]*ka.x + q[i][1]*ka.y + q[i][2]*ka.z + q[i][3]*ka.w
                    + q[i][4]*kb.x + q[i][5]*kb.y + q[i][6]*kb.z + q[i][7]*kb.w
                    + q[i][8]*kc.x + q[i][9]*kc.y + q[i][10]*kc.z + q[i][11]*kc.w;
            p[i] = ex2(s);
            if (i == J && mm > t) p[i] = 0.f;
            d[i] += p[i];
        }
        float4 va = sv[3*mm], vb = sv[3*mm+1], vc = sv[3*mm+2];
#pragma unroll
        for (int i = 0; i < 4; i++) {
            if (i < J) continue;
            o[i][0] += p[i]*va.x; o[i][1] += p[i]*va.y; o[i][2]  += p[i]*va.z; o[i][3]  += p[i]*va.w;
            o[i][4] += p[i]*vb.x; o[i][5] += p[i]*vb.y; o[i][6]  += p[i]*vb.z; o[i][7]  += p[i]*vb.w;
            o[i][8] += p[i]*vc.x; o[i][9] += p[i]*vc.y; o[i][10] += p[i]*vc.z; o[i][11] += p[i]*vc.w;
        }
    }
}

__global__ void attn_kernel()
{
    __shared__ float4 sk[128 * 3];
    __shared__ float4 sv[128 * 3];
    int qt = gridDim.x - 1 - blockIdx.x;    // heavy tiles first
    int h = blockIdx.y, bb = blockIdx.z;
    int t = threadIdx.x;

    size_t head = ((size_t)bb * Hc + h) * Lc * Kc;
    const float4* qb = (const float4*)(g_q + head);
    const float*  kb = g_k + head;
    const float*  vb = g_v + head;

    const float scale = 0.4164682333693345f;   // log2(e)/sqrt(12)
    float q[4][12], o[4][12], d[4];
#pragma unroll
    for (int i = 0; i < 4; i++) {
        int l = qt * 512 + t + 128 * i;
        float4 a = qb[3*l], b = qb[3*l+1], c = qb[3*l+2];
        q[i][0]=a.x*scale; q[i][1]=a.y*scale; q[i][2]=a.z*scale; q[i][3]=a.w*scale;
        q[i][4]=b.x*scale; q[i][5]=b.y*scale; q[i][6]=b.z*scale; q[i][7]=b.w*scale;
        q[i][8]=c.x*scale; q[i][9]=c.y*scale; q[i][10]=c.z*scale; q[i][11]=c.w*scale;
        d[i] = 0.f;
#pragma unroll
        for (int j = 0; j < 12; j++) o[i][j] = 0.f;
    }

    int full = 4 * qt;
    for (int kt = 0; kt < full + 4; kt++) {
        __syncthreads();
        const float4* ks = (const float4*)(kb + (size_t)kt * 128 * Kc);
        const float4* vs = (const float4*)(vb + (size_t)kt * 128 * Kc);
        for (int i = t; i < 128 * 3; i += 128) { sk[i] = ks[i]; sv[i] = vs[i]; }
        __syncthreads();
        if      (kt <  full)     attn_tile4<-1>(sk, sv, t, q, o, d);  // all full
        else if (kt == full)     attn_tile4<0>(sk, sv, t, q, o, d);
        else if (kt == full + 1) attn_tile4<1>(sk, sv, t, q, o, d);
        else if (kt == full + 2) attn_tile4<2>(sk, sv, t, q, o, d);
        else                     attn_tile4<3>(sk, sv, t, q, o, d);
    }

#pragma unroll
    for (int i = 0; i < 4; i++) {
        float inv = 1.f / d[i];
        int l = qt * 512 + t + 128 * i;
        float4* out = (float4*)(g_ctx + (((size_t)bb * Lc + l) * Hc + h) * Kc);
        out[0] = make_float4(o[i][0]*inv, o[i][1]*inv, o[i][2]*inv,  o[i][3]*inv);
        out[1] = make_float4(o[i][4]*inv, o[i][5]*inv, o[i][6]*inv,  o[i][7]*inv);
        out[2] = make_float4(o[i][8]*inv, o[i][9]*inv, o[i][10]*inv, o[i][11]*inv);
    }
}

// ---------------- output projection + residual + fused LN2: tf32 MMA ----------
// M=64/block, N=192, K=48. 256 threads = 8 warps. After MMA: stage y1 in smem,
// row-wise LN -> g_xn (xn2, fp32); g_y1 written from registers.
#define PA_S 52
#define PB_S 200
#define PA_FLOATS (64 * PA_S)
#define PB_FLOATS (48 * PB_S)
#define PST_S 196
#define PROJ_SMEM_BYTES ((PA_FLOATS + PB_FLOATS) * 4)   // 12928 floats > 64*196

__global__ __launch_bounds__(256, 4)
void proj_mma_kernel(const float* __restrict__ x,
                     const float* __restrict__ wo,
                     const float* __restrict__ bo,
                     const float* __restrict__ ln_g,
                     const float* __restrict__ ln_b)
{
    extern __shared__ float smem[];
    float* sA = smem;                 // [64][52]  ctx rows, tf32
    float* sB = smem + PA_FLOATS;     // [48][200] wo, tf32

    const int tid  = threadIdx.x;
    const int w    = tid >> 5;
    const int lane = tid & 31;
    const int tig  = lane & 3;
    const int grp  = lane >> 2;
    const int rowbase = blockIdx.x * 64;

    for (int idx = tid; idx < 64 * 12; idx += 256) {
        int r = idx / 12, c4 = (idx % 12) * 4;
        float4 v = *(const float4*)(g_ctx + (size_t)(rowbase + r) * 48 + c4);
        float* d = sA + r * PA_S + c4;
        d[0] = to_tf32(v.x); d[1] = to_tf32(v.y);
        d[2] = to_tf32(v.z); d[3] = to_tf32(v.w);
    }
    for (int idx = tid; idx < 48 * 48; idx += 256) {
        int r = idx / 48, c4 = (idx % 48) * 4;
        float4 v = *(const float4*)(wo + (size_t)r * Dc + c4);
        float* d = sB + r * PB_S + c4;
        d[0] = to_tf32(v.x); d[1] = to_tf32(v.y);
        d[2] = to_tf32(v.z); d[3] = to_tf32(v.w);
    }
    __syncthreads();

    const int mbase = (w & 1) * 32;
    const int nbase = (w >> 1) * 48;
    float c[2][6][4];
#pragma unroll
    for (int i = 0; i < 2; i++)
#pragma unroll
        for (int j = 0; j < 6; j++)
#pragma unroll
            for (int q = 0; q < 4; q++) c[i][j][q] = 0.f;

#pragma unroll
    for (int ks = 0; ks < 6; ks++) {
        const int c0 = ks * 8;
        uint32_t a[2][4];
#pragma unroll
        for (int mt = 0; mt < 2; mt++) {
            const float* ap = sA + (mbase + mt * 16 + grp) * PA_S + c0 + tig;
            a[mt][0] = __float_as_uint(ap[0]);
            a[mt][1] = __float_as_uint(ap[8 * PA_S]);
            a[mt][2] = __float_as_uint(ap[4]);
            a[mt][3] = __float_as_uint(ap[8 * PA_S + 4]);
        }
        const float* bp = sB + (c0 + tig) * PB_S + nbase + grp;
#pragma unroll
        for (int nt = 0; nt < 6; nt++) {
            uint32_t b0 = __float_as_uint(bp[nt * 8]);
            uint32_t b1 = __float_as_uint(bp[nt * 8 + 4 * PB_S]);
            mma_tf32(c[0][nt], a[0], b0, b1);
            mma_tf32(c[1][nt], a[1], b0, b1);
        }
    }
    __syncthreads();                       // done with sA/sB; reuse as stage

    float* stage = smem;                   // [64][196]
#pragma unroll
    for (int mt = 0; mt < 2; mt++) {
#pragma unroll
        for (int rs = 0; rs < 2; rs++) {
            int r = mbase + mt * 16 + grp + rs * 8;
            size_t off = (size_t)(rowbase + r) * Dc;
#pragma unroll
            for (int nt = 0; nt < 6; nt++) {
                int n = nbase + nt * 8 + tig * 2;
                float2 xv = *(const float2*)(x + off + n);
                float2 res;
                res.x = c[mt][nt][rs * 2 + 0] + bo[n]     + xv.x;
                res.y = c[mt][nt][rs * 2 + 1] + bo[n + 1] + xv.y;
                *(float2*)(g_y1 + off + n) = res;
                *(float2*)(stage + r * PST_S + n) = res;
            }
        }
    }
    __syncthreads();

    // fused LN2: warp w handles rows w, w+8, ... -> g_xn (fp32)
    for (int r = w; r < 64; r += 8) {
        float vv[6]; float s = 0.f;
#pragma unroll
        for (int i = 0; i < 6; i++) { vv[i] = stage[r * PST_S + lane + 32*i]; s += vv[i]; }
#pragma unroll
        for (int o = 16; o; o >>= 1) s += __shfl_xor_sync(0xffffffffu, s, o);
        float mean = s * (1.f/192.f);
        float vs = 0.f;
#pragma unroll
        for (int i = 0; i < 6; i++) { float dd = vv[i] - mean; vs += dd*dd; }
#pragma unroll
        for (int o = 16; o; o >>= 1) vs += __shfl_xor_sync(0xffffffffu, vs, o);
        float inv = rsqrtf(vs * (1.f/192.f) + 1e-3f);
#pragma unroll
        for (int i = 0; i < 6; i++) {
            int cc = lane + 32*i;
            g_xn[(size_t)(rowbase + r) * Dc + cc] =
                (vv[i] - mean) * inv * ln_g[cc] + ln_b[cc];
        }
    }
}

// ---------------- conv1d as tf32 tensor-core GEMM ----------------
#define SA_STRIDE 196
#define SB_STRIDE 200
#define SA_FLOATS (66 * SA_STRIDE)
#define SB_FLOATS (32 * SB_STRIDE)
#define CONV_SMEM_BYTES ((SA_FLOATS + 2 * SB_FLOATS) * 4)

template<int MODE>
__global__ __launch_bounds__(256, 2)
void conv_mma_kernel(const float* __restrict__ W,
                     const float* __restrict__ bias,
                     float* __restrict__ out)
{
    extern __shared__ float smem[];
    float* sA = smem;                    // [66][196]
    float* sB = smem + SA_FLOATS;        // [2][32][200]

    const int tid  = threadIdx.x;
    const int w    = tid >> 5;
    const int lane = tid & 31;
    const int tig  = lane & 3;
    const int grp  = lane >> 2;
    const int l0   = blockIdx.x * 64;
    const int bb   = blockIdx.y;
    const float* srcb = ((MODE == 0) ? g_xn : g_h) + (size_t)bb * Lc * Dc;

    for (int idx = tid; idx < 66 * 48; idx += 256) {
        int r = idx / 48, c4 = (idx % 48) * 4;
        int l = l0 - 1 + r; l = l < 0 ? 0 : (l > Lc - 1 ? Lc - 1 : l);
        float4 v = *(const float4*)(srcb + (size_t)l * Dc + c4);
        float* d = sA + r * SA_STRIDE + c4;
        d[0] = to_tf32(v.x); d[1] = to_tf32(v.y);
        d[2] = to_tf32(v.z); d[3] = to_tf32(v.w);
    }

    const int mbase = (w & 1) * 32;
    const int nbase = (w >> 1) * 48;
    float c[2][6][4];
#pragma unroll
    for (int i = 0; i < 2; i++)
#pragma unroll
        for (int j = 0; j < 6; j++)
#pragma unroll
            for (int q = 0; q < 4; q++) c[i][j][q] = 0.f;

    auto loadW = [&](int kc, int bf) {
        float* dstb = sB + bf * SB_FLOATS;
#pragma unroll
        for (int it = 0; it < 6; it++) {
            int idx = tid + it * 256;
            int k = idx / 48, c4 = (idx % 48) * 4;
            float4 v = *(const float4*)(W + ((size_t)(kc * 32 + k)) * Dc + c4);
            float* d = dstb + k * SB_STRIDE + c4;
            d[0] = to_tf32(v.x); d[1] = to_tf32(v.y);
            d[2] = to_tf32(v.z); d[3] = to_tf32(v.w);
        }
    };

    loadW(0, 0);
    __syncthreads();

    int buf = 0;
    for (int kc = 0; kc < 18; kc++) {
        if (kc < 17) loadW(kc + 1, buf ^ 1);
        const int t  = kc / 6;
        const int cc = (kc % 6) * 32;
        const float* bBuf = sB + buf * SB_FLOATS;
#pragma unroll
        for (int ks = 0; ks < 4; ks++) {
            const int c0 = cc + ks * 8;
            uint32_t a[2][4];
#pragma unroll
            for (int mt = 0; mt < 2; mt++) {
                const float* ap = sA + (mbase + mt * 16 + grp + t) * SA_STRIDE + c0 + tig;
                a[mt][0] = __float_as_uint(ap[0]);
                a[mt][1] = __float_as_uint(ap[8 * SA_STRIDE]);
                a[mt][2] = __float_as_uint(ap[4]);
                a[mt][3] = __float_as_uint(ap[8 * SA_STRIDE + 4]);
            }
            const float* bp = bBuf + (ks * 8 + tig) * SB_STRIDE + nbase + grp;
#pragma unroll
            for (int nt = 0; nt < 6; nt++) {
                uint32_t b0 = __float_as_uint(bp[nt * 8]);
                uint32_t b1 = __float_as_uint(bp[nt * 8 + 4 * SB_STRIDE]);
                mma_tf32(c[0][nt], a[0], b0, b1);
                mma_tf32(c[1][nt], a[1], b0, b1);
            }
        }
        __syncthreads();
        buf ^= 1;
    }

    float* dst = (MODE == 0) ? g_h : out;
#pragma unroll
    for (int mt = 0; mt < 2; mt++) {
#pragma unroll
        for (int rs = 0; rs < 2; rs++) {
            int l = l0 + mbase + mt * 16 + grp + rs * 8;
            bool interior = (l >= 1) && (l <= Lc - 2);
            size_t rowoff = ((size_t)bb * Lc + l) * Dc;
#pragma unroll
            for (int nt = 0; nt < 6; nt++) {
                int n = nbase + nt * 8 + tig * 2;
                float v0 = c[mt][nt][rs * 2 + 0] + bias[n];
                float v1 = c[mt][nt][rs * 2 + 1] + bias[n + 1];
                float2 res;
                if (MODE == 0) {
                    res.x = interior ? fmaxf(v0, 0.f) : 0.f;
                    res.y = interior ? fmaxf(v1, 0.f) : 0.f;
                } else {
                    float2 y = *(const float2*)(g_y1 + rowoff + n);
                    res.x = y.x + (interior ? v0 : 0.f);
                    res.y = y.y + (interior ? v1 : 0.f);
                }
                *(float2*)(dst + rowoff + n) = res;
            }
        }
    }
}

// ---------------- launcher ----------------
extern "C" void kernel_launch(void* const* d_in, const int* in_sizes, int n_in,
                              void* d_out, int out_size)
{
    const float* x     = (const float*)d_in[0];
    const float* ln1_g = (const float*)d_in[1];
    const float* ln1_b = (const float*)d_in[2];
    const float* wq    = (const float*)d_in[3];
    const float* bq    = (const float*)d_in[4];
    const float* wk    = (const float*)d_in[5];
    const float* bk    = (const float*)d_in[6];
    const float* wv    = (const float*)d_in[7];
    const float* bv    = (const float*)d_in[8];
    const float* wo    = (const float*)d_in[9];
    const float* bo    = (const float*)d_in[10];
    const float* ln2_g = (const float*)d_in[11];
    const float* ln2_b = (const float*)d_in[12];
    const float* c1_w  = (const float*)d_in[13];
    const float* c1_b  = (const float*)d_in[14];
    const float* c2_w  = (const float*)d_in[15];
    const float* c2_b  = (const float*)d_in[16];
    float* outp = (float*)d_out;

    cudaFuncSetAttribute(conv_mma_kernel<0>,
                         cudaFuncAttributeMaxDynamicSharedMemorySize, CONV_SMEM_BYTES);
    cudaFuncSetAttribute(conv_mma_kernel<1>,
                         cudaFuncAttributeMaxDynamicSharedMemorySize, CONV_SMEM_BYTES);
    cudaFuncSetAttribute(qkv_mma_kernel,
                         cudaFuncAttributeMaxDynamicSharedMemorySize, QKV_SMEM_BYTES);
    cudaFuncSetAttribute(proj_mma_kernel,
                         cudaFuncAttributeMaxDynamicSharedMemorySize, PROJ_SMEM_BYTES);

    qkv_mma_kernel<<<(Bc*Lc)/64, 192, QKV_SMEM_BYTES>>>(x, ln1_g, ln1_b,
                                                        wq, bq, wk, bk, wv, bv);
    attn_kernel<<<dim3(Lc/512, Hc, Bc), 128>>>();
    proj_mma_kernel<<<(Bc*Lc)/64, 256, PROJ_SMEM_BYTES>>>(x, wo, bo, ln2_g, ln2_b);
    conv_mma_kernel<0><<<dim3(Lc/64, Bc), 256, CONV_SMEM_BYTES>>>(c1_w, c1_b, outp);
    conv_mma_kernel<1><<<dim3(Lc/64, Bc), 256, CONV_SMEM_BYTES>>>(c2_w, c2_b, outp);
}